// round 2
// baseline (speedup 1.0000x reference)
#include <cuda_runtime.h>
#include <math.h>

#define NPAPER  100000
#define NAUTHOR 50000
#define NEDGE   400000
#define HDIM    256
#define NHEADS  8
#define HD      32

// ---------------- scratch (device globals; no allocation allowed) ----------
__device__ float g_q0[NPAPER * HDIM];
__device__ float g_k0[NAUTHOR * HDIM];
__device__ float g_v0[NAUTHOR * HDIM];
__device__ float g_q1[NAUTHOR * HDIM];
__device__ float g_k1[NPAPER * HDIM];
__device__ float g_v1[NPAPER * HDIM];
__device__ float g_q2[NPAPER * HDIM];
__device__ float g_k2[NPAPER * HDIM];
__device__ float g_v2[NPAPER * HDIM];
__device__ float g_attn0[NEDGE * NHEADS];
__device__ float g_attn1[NEDGE * NHEADS];
__device__ float g_attn2[NEDGE * NHEADS];
__device__ float g_aggw[NPAPER * HDIM];
__device__ float g_aggwr[NAUTHOR * HDIM];
__device__ float g_aggc[NPAPER * HDIM];
__device__ float g_tmp_p[NPAPER * HDIM];
__device__ float g_tmp_a[NAUTHOR * HDIM];

// ---------------- GEMM: C[M,256] = (w0*A0 + w1*A1) @ W + bias --------------
// BM=128, BN=128, BK=16, 256 threads, 8x8 register tile (split 4+4 halves),
// double-buffered smem with a single __syncthreads per K-tile.
#define BK 16

__global__ void __launch_bounds__(256) gemm_fused(
    const float* __restrict__ A0, const float* __restrict__ A1,
    const float* __restrict__ wsm,   // if non-null: 2-way softmax weights
    const float* __restrict__ W, const float* __restrict__ bias,
    float* __restrict__ C, int M)
{
    __shared__ float As[2][BK][128];
    __shared__ float Bs[2][BK][128];

    const int tid = threadIdx.x;
    const int bm = blockIdx.x * 128;
    const int bn = blockIdx.y * 128;

    float w0 = 1.f, w1 = 0.f;
    if (wsm) {
        float a = wsm[0], b = wsm[1];
        float mx = fmaxf(a, b);
        float e0 = expf(a - mx), e1 = expf(b - mx);
        float inv = 1.f / (e0 + e1);
        w0 = e0 * inv; w1 = e1 * inv;
    }

    // ---- load mappings ----
    const int am  = tid >> 1;          // 0..127  (A row within tile)
    const int ak  = (tid & 1) * 8;     // 0 or 8  (A k-seg, 8 floats)
    const int bkr = tid >> 5;          // 0..7    (B k row; also +8)
    const int bcol = (tid & 31) * 4;   // 0..124

    // ---- compute mapping: rows {tm..tm+3, tm+64..}, cols {tn.., tn+64..} ----
    const int tm = (tid >> 4) * 4;     // 0..60
    const int tn = (tid & 15) * 4;     // 0..60

    const bool arow_ok = (bm + am) < M;
    const float* Arow0 = A0 + (size_t)(bm + am) * HDIM;
    const float* Arow1 = A1 ? (A1 + (size_t)(bm + am) * HDIM) : nullptr;

    float acc[8][8];
#pragma unroll
    for (int i = 0; i < 8; ++i)
#pragma unroll
        for (int j = 0; j < 8; ++j) acc[i][j] = 0.f;

    float4 av0, av1, bv0, bv1;

    auto load_tile = [&](int k0) {
        av0 = make_float4(0.f, 0.f, 0.f, 0.f);
        av1 = make_float4(0.f, 0.f, 0.f, 0.f);
        if (arow_ok) {
            float4 a0 = *(const float4*)(Arow0 + k0 + ak);
            float4 a1 = *(const float4*)(Arow0 + k0 + ak + 4);
            if (Arow1) {
                float4 c0 = *(const float4*)(Arow1 + k0 + ak);
                float4 c1 = *(const float4*)(Arow1 + k0 + ak + 4);
                av0 = make_float4(w0*a0.x + w1*c0.x, w0*a0.y + w1*c0.y,
                                  w0*a0.z + w1*c0.z, w0*a0.w + w1*c0.w);
                av1 = make_float4(w0*a1.x + w1*c1.x, w0*a1.y + w1*c1.y,
                                  w0*a1.z + w1*c1.z, w0*a1.w + w1*c1.w);
            } else {
                av0 = make_float4(w0*a0.x, w0*a0.y, w0*a0.z, w0*a0.w);
                av1 = make_float4(w0*a1.x, w0*a1.y, w0*a1.z, w0*a1.w);
            }
        }
        bv0 = *(const float4*)(W + (size_t)(k0 + bkr) * HDIM + bn + bcol);
        bv1 = *(const float4*)(W + (size_t)(k0 + bkr + 8) * HDIM + bn + bcol);
    };

    auto store_tile = [&](int buf) {
        As[buf][ak + 0][am] = av0.x;
        As[buf][ak + 1][am] = av0.y;
        As[buf][ak + 2][am] = av0.z;
        As[buf][ak + 3][am] = av0.w;
        As[buf][ak + 4][am] = av1.x;
        As[buf][ak + 5][am] = av1.y;
        As[buf][ak + 6][am] = av1.z;
        As[buf][ak + 7][am] = av1.w;
        *(float4*)&Bs[buf][bkr][bcol]     = bv0;
        *(float4*)&Bs[buf][bkr + 8][bcol] = bv1;
    };

    load_tile(0);
    store_tile(0);
    __syncthreads();

    const int T = HDIM / BK;
    for (int t = 0; t < T; ++t) {
        const int buf = t & 1;
        if (t + 1 < T) load_tile((t + 1) * BK);

#pragma unroll
        for (int k = 0; k < BK; ++k) {
            float a[8], b[8];
            *(float4*)(a)     = *(const float4*)&As[buf][k][tm];
            *(float4*)(a + 4) = *(const float4*)&As[buf][k][tm + 64];
            *(float4*)(b)     = *(const float4*)&Bs[buf][k][tn];
            *(float4*)(b + 4) = *(const float4*)&Bs[buf][k][tn + 64];
#pragma unroll
            for (int i = 0; i < 8; ++i)
#pragma unroll
                for (int j = 0; j < 8; ++j) acc[i][j] += a[i] * b[j];
        }

        if (t + 1 < T) {
            store_tile(buf ^ 1);
            __syncthreads();
        }
    }

    // epilogue
#pragma unroll
    for (int ih = 0; ih < 2; ++ih) {
#pragma unroll
        for (int i = 0; i < 4; ++i) {
            int row = bm + tm + ih * 64 + i;
            if (row < M) {
#pragma unroll
                for (int jh = 0; jh < 2; ++jh) {
                    int col = bn + tn + jh * 64;
                    float4 o;
                    o.x = acc[ih*4+i][jh*4+0] + bias[col + 0];
                    o.y = acc[ih*4+i][jh*4+1] + bias[col + 1];
                    o.z = acc[ih*4+i][jh*4+2] + bias[col + 2];
                    o.w = acc[ih*4+i][jh*4+3] + bias[col + 3];
                    *(float4*)&C[(size_t)row * HDIM + col] = o;
                }
            }
        }
    }
}

// ---------------- edge attention scores: warp per edge ---------------------
__global__ void __launch_bounds__(256) edge_attn_kernel(
    const float* __restrict__ q, const float* __restrict__ k,
    const int* __restrict__ src, const int* __restrict__ dst,
    const float* __restrict__ eattn, float* __restrict__ attn, int E)
{
    int e = (blockIdx.x * blockDim.x + threadIdx.x) >> 5;
    int lane = threadIdx.x & 31;
    if (e >= E) return;
    int s = src[e], d = dst[e];
    const float4* qp = (const float4*)(q + (size_t)d * HDIM) + lane * 2;
    const float4* kp = (const float4*)(k + (size_t)s * HDIM) + lane * 2;
    float4 q0 = qp[0], q1 = qp[1];
    float4 k0 = kp[0], k1 = kp[1];
    float p = q0.x * k0.x + q0.y * k0.y + q0.z * k0.z + q0.w * k0.w +
              q1.x * k1.x + q1.y * k1.y + q1.z * k1.z + q1.w * k1.w;
    // reduce within 4-lane groups (one head per group)
    p += __shfl_xor_sync(0xffffffffu, p, 1);
    p += __shfl_xor_sync(0xffffffffu, p, 2);
    if ((lane & 3) == 0) {
        int h = lane >> 2;
        attn[(size_t)e * NHEADS + h] = p * 0.17677669529663687f + eattn[h];
    }
}

// ---------------- segmented softmax + V aggregation: warp per dst node -----
__device__ __forceinline__ int lower_bound_i(const int* __restrict__ a, int n, int key)
{
    int lo = 0, hi = n;
    while (lo < hi) {
        int mid = (lo + hi) >> 1;
        if (a[mid] < key) lo = mid + 1; else hi = mid;
    }
    return lo;
}

__global__ void __launch_bounds__(256) seg_agg_kernel(
    const float* __restrict__ attn, const float* __restrict__ v,
    const int* __restrict__ src, const int* __restrict__ dst,
    float* __restrict__ out, int n_dst, int E)
{
    int node = (blockIdx.x * blockDim.x + threadIdx.x) >> 5;
    int lane = threadIdx.x & 31;
    if (node >= n_dst) return;

    int lo = lower_bound_i(dst, E, node);
    int hi = lower_bound_i(dst, E, node + 1);

    const int h8 = lane & 7;     // head this lane tracks for softmax stats
    const int head = lane >> 2;  // head owning this lane's V dims

    // pass 1: per-head max, clamped at 0 (torch index_reduce on zeros buffer)
    float m = 0.f;
    {
        int e = lo;
        for (; e + 3 < hi; e += 4) {
            float a0 = attn[(size_t)(e + 0) * NHEADS + h8];
            float a1 = attn[(size_t)(e + 1) * NHEADS + h8];
            float a2 = attn[(size_t)(e + 2) * NHEADS + h8];
            float a3 = attn[(size_t)(e + 3) * NHEADS + h8];
            m = fmaxf(m, fmaxf(fmaxf(a0, a1), fmaxf(a2, a3)));
        }
        for (; e < hi; ++e)
            m = fmaxf(m, attn[(size_t)e * NHEADS + h8]);
    }

    // pass 2: s = sum(exp), acc = sum(exp * v); unrolled x2 for MLP
    float s = 0.f;
    float acc[8] = {0.f, 0.f, 0.f, 0.f, 0.f, 0.f, 0.f, 0.f};
    int e = lo;
    for (; e + 1 < hi; e += 2) {
        float a0 = attn[(size_t)(e + 0) * NHEADS + h8];
        float a1 = attn[(size_t)(e + 1) * NHEADS + h8];
        int s0 = src[e], s1 = src[e + 1];
        const float4* vp0 = (const float4*)(v + (size_t)s0 * HDIM) + lane * 2;
        const float4* vp1 = (const float4*)(v + (size_t)s1 * HDIM) + lane * 2;
        float4 x0 = vp0[0], x1 = vp0[1];
        float4 y0 = vp1[0], y1 = vp1[1];
        float ev0 = __expf(a0 - m);
        float ev1 = __expf(a1 - m);
        s += ev0 + ev1;
        float w0 = __shfl_sync(0xffffffffu, ev0, head);
        float w1 = __shfl_sync(0xffffffffu, ev1, head);
        acc[0] += w0 * x0.x + w1 * y0.x;
        acc[1] += w0 * x0.y + w1 * y0.y;
        acc[2] += w0 * x0.z + w1 * y0.z;
        acc[3] += w0 * x0.w + w1 * y0.w;
        acc[4] += w0 * x1.x + w1 * y1.x;
        acc[5] += w0 * x1.y + w1 * y1.y;
        acc[6] += w0 * x1.z + w1 * y1.z;
        acc[7] += w0 * x1.w + w1 * y1.w;
    }
    if (e < hi) {
        float a0 = attn[(size_t)e * NHEADS + h8];
        int s0 = src[e];
        const float4* vp0 = (const float4*)(v + (size_t)s0 * HDIM) + lane * 2;
        float4 x0 = vp0[0], x1 = vp0[1];
        float ev0 = __expf(a0 - m);
        s += ev0;
        float w0 = __shfl_sync(0xffffffffu, ev0, head);
        acc[0] += w0 * x0.x; acc[1] += w0 * x0.y; acc[2] += w0 * x0.z; acc[3] += w0 * x0.w;
        acc[4] += w0 * x1.x; acc[5] += w0 * x1.y; acc[6] += w0 * x1.z; acc[7] += w0 * x1.w;
    }
    float sh = __shfl_sync(0xffffffffu, s, head);
    float inv = 1.f / fmaxf(sh, 1e-9f);

    float* op = out + (size_t)node * HDIM + lane * 8;
    *(float4*)op       = make_float4(acc[0] * inv, acc[1] * inv, acc[2] * inv, acc[3] * inv);
    *(float4*)(op + 4) = make_float4(acc[4] * inv, acc[5] * inv, acc[6] * inv, acc[7] * inv);
}

// ---------------- residual + LayerNorm: warp per row -----------------------
__global__ void __launch_bounds__(256) ln_kernel(
    const float* __restrict__ x, const float* __restrict__ t,
    const float* __restrict__ g, const float* __restrict__ b,
    float* __restrict__ out, int M)
{
    int row = (blockIdx.x * blockDim.x + threadIdx.x) >> 5;
    int lane = threadIdx.x & 31;
    if (row >= M) return;

    const float4* xp = (const float4*)(x + (size_t)row * HDIM) + lane * 2;
    const float4* tp = (const float4*)(t + (size_t)row * HDIM) + lane * 2;
    float4 a0 = xp[0], a1 = xp[1], c0 = tp[0], c1 = tp[1];
    float vals[8];
    vals[0] = a0.x + c0.x; vals[1] = a0.y + c0.y; vals[2] = a0.z + c0.z; vals[3] = a0.w + c0.w;
    vals[4] = a1.x + c1.x; vals[5] = a1.y + c1.y; vals[6] = a1.z + c1.z; vals[7] = a1.w + c1.w;

    float sum = 0.f, sq = 0.f;
#pragma unroll
    for (int j = 0; j < 8; ++j) { sum += vals[j]; sq += vals[j] * vals[j]; }
#pragma unroll
    for (int o = 16; o; o >>= 1) {
        sum += __shfl_xor_sync(0xffffffffu, sum, o);
        sq  += __shfl_xor_sync(0xffffffffu, sq,  o);
    }
    float mean = sum * (1.f / HDIM);
    float var  = sq * (1.f / HDIM) - mean * mean;
    float inv  = rsqrtf(var + 1e-5f);

    const float4* gp = (const float4*)(g) + lane * 2;
    const float4* bp = (const float4*)(b) + lane * 2;
    float4 g0 = gp[0], g1 = gp[1], bb0 = bp[0], bb1 = bp[1];

    float* op = out + (size_t)row * HDIM + lane * 8;
    float4 o0, o1;
    o0.x = (vals[0] - mean) * inv * g0.x + bb0.x;
    o0.y = (vals[1] - mean) * inv * g0.y + bb0.y;
    o0.z = (vals[2] - mean) * inv * g0.z + bb0.z;
    o0.w = (vals[3] - mean) * inv * g0.w + bb0.w;
    o1.x = (vals[4] - mean) * inv * g1.x + bb1.x;
    o1.y = (vals[5] - mean) * inv * g1.y + bb1.y;
    o1.z = (vals[6] - mean) * inv * g1.z + bb1.z;
    o1.w = (vals[7] - mean) * inv * g1.w + bb1.w;
    *(float4*)op       = o0;
    *(float4*)(op + 4) = o1;
}

// ---------------------------------------------------------------------------
extern "C" void kernel_launch(void* const* d_in, const int* in_sizes, int n_in,
                              void* d_out, int out_size)
{
    const float* x_paper  = (const float*)d_in[0];
    const float* x_author = (const float*)d_in[1];
    const int* w_src  = (const int*)d_in[2];
    const int* w_dst  = (const int*)d_in[3];
    const int* wr_src = (const int*)d_in[4];
    const int* wr_dst = (const int*)d_in[5];
    const int* c_src  = (const int*)d_in[6];
    const int* c_dst  = (const int*)d_in[7];
    const float* Wq = (const float*)d_in[8];
    const float* bq = (const float*)d_in[9];
    const float* Wk = (const float*)d_in[10];
    const float* bk = (const float*)d_in[11];
    const float* Wv = (const float*)d_in[12];
    const float* bv = (const float*)d_in[13];
    const float* eattn = (const float*)d_in[14];
    const float* Wout_p = (const float*)d_in[15];
    const float* bout_p = (const float*)d_in[16];
    const float* Wout_a = (const float*)d_in[17];
    const float* bout_a = (const float*)d_in[18];
    const float* lng_p = (const float*)d_in[19];
    const float* lnb_p = (const float*)d_in[20];
    const float* lng_a = (const float*)d_in[21];
    const float* lnb_a = (const float*)d_in[22];
    const float* w_paper = (const float*)d_in[23];
    // d_in[24] = w_author (softmax of 1 element == 1.0, unused)

    float* out = (float*)d_out;

    float *q0, *k0, *v0, *q1, *k1, *v1, *q2, *k2, *v2;
    float *at0, *at1, *at2, *aw, *awr, *ac, *tp, *ta;
    cudaGetSymbolAddress((void**)&q0, g_q0);
    cudaGetSymbolAddress((void**)&k0, g_k0);
    cudaGetSymbolAddress((void**)&v0, g_v0);
    cudaGetSymbolAddress((void**)&q1, g_q1);
    cudaGetSymbolAddress((void**)&k1, g_k1);
    cudaGetSymbolAddress((void**)&v1, g_v1);
    cudaGetSymbolAddress((void**)&q2, g_q2);
    cudaGetSymbolAddress((void**)&k2, g_k2);
    cudaGetSymbolAddress((void**)&v2, g_v2);
    cudaGetSymbolAddress((void**)&at0, g_attn0);
    cudaGetSymbolAddress((void**)&at1, g_attn1);
    cudaGetSymbolAddress((void**)&at2, g_attn2);
    cudaGetSymbolAddress((void**)&aw, g_aggw);
    cudaGetSymbolAddress((void**)&awr, g_aggwr);
    cudaGetSymbolAddress((void**)&ac, g_aggc);
    cudaGetSymbolAddress((void**)&tp, g_tmp_p);
    cudaGetSymbolAddress((void**)&ta, g_tmp_a);

    const int HH = HDIM * HDIM;

    auto gemm = [&](const float* A0, const float* A1, const float* wsm,
                    const float* W, const float* bias, float* C, int M) {
        dim3 grid((M + 127) / 128, HDIM / 128);
        gemm_fused<<<grid, 256>>>(A0, A1, wsm, W, bias, C, M);
    };

    // projections (rel 0: writes, rel 1: written_by, rel 2: cites)
    gemm(x_paper,  nullptr, nullptr, Wq + 0 * HH, bq + 0 * HDIM, q0, NPAPER);
    gemm(x_author, nullptr, nullptr, Wk + 0 * HH, bk + 0 * HDIM, k0, NAUTHOR);
    gemm(x_author, nullptr, nullptr, Wv + 0 * HH, bv + 0 * HDIM, v0, NAUTHOR);
    gemm(x_author, nullptr, nullptr, Wq + 1 * HH, bq + 1 * HDIM, q1, NAUTHOR);
    gemm(x_paper,  nullptr, nullptr, Wk + 1 * HH, bk + 1 * HDIM, k1, NPAPER);
    gemm(x_paper,  nullptr, nullptr, Wv + 1 * HH, bv + 1 * HDIM, v1, NPAPER);
    gemm(x_paper,  nullptr, nullptr, Wq + 2 * HH, bq + 2 * HDIM, q2, NPAPER);
    gemm(x_paper,  nullptr, nullptr, Wk + 2 * HH, bk + 2 * HDIM, k2, NPAPER);
    gemm(x_paper,  nullptr, nullptr, Wv + 2 * HH, bv + 2 * HDIM, v2, NPAPER);

    // edge attention scores
    int eblocks = (NEDGE * 32 + 255) / 256;
    edge_attn_kernel<<<eblocks, 256>>>(q0, k0, w_src,  w_dst,  eattn + 0,  at0, NEDGE);
    edge_attn_kernel<<<eblocks, 256>>>(q1, k1, wr_src, wr_dst, eattn + 8,  at1, NEDGE);
    edge_attn_kernel<<<eblocks, 256>>>(q2, k2, c_src,  c_dst,  eattn + 16, at2, NEDGE);

    // segmented softmax + aggregation
    seg_agg_kernel<<<(NPAPER * 32 + 255) / 256, 256>>>(at0, v0, w_src,  w_dst,  aw,  NPAPER,  NEDGE);
    seg_agg_kernel<<<(NAUTHOR * 32 + 255) / 256, 256>>>(at1, v1, wr_src, wr_dst, awr, NAUTHOR, NEDGE);
    seg_agg_kernel<<<(NPAPER * 32 + 255) / 256, 256>>>(at2, v2, c_src,  c_dst,  ac,  NPAPER,  NEDGE);

    // output projections (paper combines writes+cites with softmax(w_paper))
    gemm(aw,  ac,      w_paper, Wout_p, bout_p, tp, NPAPER);
    gemm(awr, nullptr, nullptr, Wout_a, bout_a, ta, NAUTHOR);

    // residual + layernorm -> packed output [paper | author]
    ln_kernel<<<(NPAPER * 32 + 255) / 256, 256>>>(x_paper, tp, lng_p, lnb_p, out, NPAPER);
    ln_kernel<<<(NAUTHOR * 32 + 255) / 256, 256>>>(x_author, ta, lng_a, lnb_a,
                                                   out + (size_t)NPAPER * HDIM, NAUTHOR);
}

// round 4
// speedup vs baseline: 1.3624x; 1.3624x over previous
#include <cuda_runtime.h>
#include <math.h>

#define NPAPER  100000
#define NAUTHOR 50000
#define NEDGE   400000
#define HDIM    256
#define NHEADS  8
#define HD      32

// ---------------- scratch (device globals; no allocation allowed) ----------
__device__ float g_q0[NPAPER * HDIM];
__device__ float g_k0[NAUTHOR * HDIM];
__device__ float g_v0[NAUTHOR * HDIM];
__device__ float g_q1[NAUTHOR * HDIM];
__device__ float g_k1[NPAPER * HDIM];
__device__ float g_v1[NPAPER * HDIM];
__device__ float g_q2[NPAPER * HDIM];
__device__ float g_k2[NPAPER * HDIM];
__device__ float g_v2[NPAPER * HDIM];
__device__ float g_attn0[NEDGE * NHEADS];
__device__ float g_attn1[NEDGE * NHEADS];
__device__ float g_attn2[NEDGE * NHEADS];
__device__ float g_aggw[NPAPER * HDIM];
__device__ float g_aggwr[NAUTHOR * HDIM];
__device__ float g_aggc[NPAPER * HDIM];
__device__ float g_tmp_p[NPAPER * HDIM];
__device__ float g_tmp_a[NAUTHOR * HDIM];

// ---------------- packed f32x2 helpers ------------------------------------
__device__ __forceinline__ unsigned long long pack2(float lo, float hi) {
    unsigned long long r;
    asm("mov.b64 %0, {%1, %2};" : "=l"(r) : "f"(lo), "f"(hi));
    return r;
}
__device__ __forceinline__ unsigned long long dup2(float v) {
    unsigned long long r;
    asm("mov.b64 %0, {%1, %1};" : "=l"(r) : "f"(v));
    return r;
}
__device__ __forceinline__ void fma2(unsigned long long& acc,
                                     unsigned long long a, unsigned long long b) {
    asm("fma.rn.f32x2 %0, %1, %2, %0;" : "+l"(acc) : "l"(a), "l"(b));
}
__device__ __forceinline__ void unpack2(unsigned long long p, float& lo, float& hi) {
    asm("mov.b64 {%0, %1}, %2;" : "=f"(lo), "=f"(hi) : "l"(p));
}

// ---------------- GEMM: C[M,256] = (w0*A0 + w1*A1) @ W + bias --------------
// BM=128, BN=128, BK=8, 256 threads, 8x8 register tile via packed f32x2 FMA.
__global__ void __launch_bounds__(256) gemm_fused(
    const float* __restrict__ A0, const float* __restrict__ A1,
    const float* __restrict__ wsm,   // if non-null: 2-way softmax weights
    const float* __restrict__ W, const float* __restrict__ bias,
    float* __restrict__ C, int M)
{
    __shared__ float As[8][128];
    __shared__ float Bs[8][128];

    const int tid = threadIdx.x;
    const int bm = blockIdx.x * 128;
    const int bn = blockIdx.y * 128;

    float w0 = 1.f, w1 = 0.f;
    if (wsm) {
        float a = wsm[0], b = wsm[1];
        float mx = fmaxf(a, b);
        float e0 = expf(a - mx), e1 = expf(b - mx);
        float inv = 1.f / (e0 + e1);
        w0 = e0 * inv; w1 = e1 * inv;
    }

    const int tm = (tid >> 4) * 8;   // 0..120
    const int tn = (tid & 15) * 8;   // 0..120

    const int arow = tid >> 1;        // 0..127
    const int aseg = (tid & 1) * 4;   // 0 or 4
    const int brow = tid >> 5;        // 0..7
    const int bcol = (tid & 31) * 4;  // 0..124

    const bool arow_ok = (bm + arow) < M;
    const float* Arow0 = A0 + (size_t)(bm + arow) * HDIM;
    const float* Arow1 = A1 ? (A1 + (size_t)(bm + arow) * HDIM) : nullptr;

    unsigned long long acc[8][4];
#pragma unroll
    for (int i = 0; i < 8; ++i)
#pragma unroll
        for (int j = 0; j < 4; ++j) acc[i][j] = 0ULL;

    for (int k0 = 0; k0 < HDIM; k0 += 8) {
        float4 av = make_float4(0.f, 0.f, 0.f, 0.f);
        if (arow_ok) {
            float4 a0 = *(const float4*)(Arow0 + k0 + aseg);
            if (Arow1) {
                float4 a1 = *(const float4*)(Arow1 + k0 + aseg);
                av = make_float4(w0 * a0.x + w1 * a1.x, w0 * a0.y + w1 * a1.y,
                                 w0 * a0.z + w1 * a1.z, w0 * a0.w + w1 * a1.w);
            } else {
                av = make_float4(w0 * a0.x, w0 * a0.y, w0 * a0.z, w0 * a0.w);
            }
        }
        float4 bv = *(const float4*)(W + (size_t)(k0 + brow) * HDIM + bn + bcol);

        __syncthreads();
        As[aseg + 0][arow] = av.x;
        As[aseg + 1][arow] = av.y;
        As[aseg + 2][arow] = av.z;
        As[aseg + 3][arow] = av.w;
        *(float4*)&Bs[brow][bcol] = bv;
        __syncthreads();

#pragma unroll
        for (int k = 0; k < 8; ++k) {
            float a[8], b[8];
            *(float4*)(a)     = *(const float4*)&As[k][tm];
            *(float4*)(a + 4) = *(const float4*)&As[k][tm + 4];
            *(float4*)(b)     = *(const float4*)&Bs[k][tn];
            *(float4*)(b + 4) = *(const float4*)&Bs[k][tn + 4];

            unsigned long long b2[4], a2[8];
#pragma unroll
            for (int j = 0; j < 4; ++j) b2[j] = pack2(b[2*j], b[2*j+1]);
#pragma unroll
            for (int i = 0; i < 8; ++i) a2[i] = dup2(a[i]);
#pragma unroll
            for (int i = 0; i < 8; ++i)
#pragma unroll
                for (int j = 0; j < 4; ++j) fma2(acc[i][j], a2[i], b2[j]);
        }
    }

#pragma unroll
    for (int i = 0; i < 8; ++i) {
        int row = bm + tm + i;
        if (row < M) {
            float o[8];
#pragma unroll
            for (int j = 0; j < 4; ++j) unpack2(acc[i][j], o[2*j], o[2*j+1]);
#pragma unroll
            for (int j = 0; j < 8; j += 4) {
                float4 ov;
                ov.x = o[j + 0] + bias[bn + tn + j + 0];
                ov.y = o[j + 1] + bias[bn + tn + j + 1];
                ov.z = o[j + 2] + bias[bn + tn + j + 2];
                ov.w = o[j + 3] + bias[bn + tn + j + 3];
                *(float4*)&C[(size_t)row * HDIM + bn + tn + j] = ov;
            }
        }
    }
}

// ---------------- edge attention scores: warp per edge ---------------------
__global__ void __launch_bounds__(256) edge_attn_kernel(
    const float* __restrict__ q, const float* __restrict__ k,
    const int* __restrict__ src, const int* __restrict__ dst,
    const float* __restrict__ eattn, float* __restrict__ attn, int E)
{
    int e = (blockIdx.x * blockDim.x + threadIdx.x) >> 5;
    int lane = threadIdx.x & 31;
    if (e >= E) return;
    int s = src[e], d = dst[e];
    const float4* qp = (const float4*)(q + (size_t)d * HDIM) + lane * 2;
    const float4* kp = (const float4*)(k + (size_t)s * HDIM) + lane * 2;
    float4 q0 = qp[0], q1 = qp[1];
    float4 k0 = kp[0], k1 = kp[1];
    float p = q0.x * k0.x + q0.y * k0.y + q0.z * k0.z + q0.w * k0.w +
              q1.x * k1.x + q1.y * k1.y + q1.z * k1.z + q1.w * k1.w;
    // reduce within 4-lane groups (one head per group)
    p += __shfl_xor_sync(0xffffffffu, p, 1);
    p += __shfl_xor_sync(0xffffffffu, p, 2);
    if ((lane & 3) == 0) {
        int h = lane >> 2;
        attn[(size_t)e * NHEADS + h] = p * 0.17677669529663687f + eattn[h];
    }
}

// ---------------- segmented softmax + V aggregation: warp per dst node -----
__device__ __forceinline__ int lower_bound_i(const int* __restrict__ a, int n, int key)
{
    int lo = 0, hi = n;
    while (lo < hi) {
        int mid = (lo + hi) >> 1;
        if (a[mid] < key) lo = mid + 1; else hi = mid;
    }
    return lo;
}

__global__ void __launch_bounds__(256) seg_agg_kernel(
    const float* __restrict__ attn, const float* __restrict__ v,
    const int* __restrict__ src, const int* __restrict__ dst,
    float* __restrict__ out, int n_dst, int E)
{
    int node = (blockIdx.x * blockDim.x + threadIdx.x) >> 5;
    int lane = threadIdx.x & 31;
    if (node >= n_dst) return;

    int lo = lower_bound_i(dst, E, node);
    int hi = lower_bound_i(dst, E, node + 1);

    const int h8 = lane & 7;     // head this lane tracks for softmax stats
    const int head = lane >> 2;  // head owning this lane's V dims

    // pass 1: per-head max, clamped at 0 (torch index_reduce on zeros buffer)
    float m = 0.f;
    for (int e = lo; e < hi; ++e)
        m = fmaxf(m, attn[(size_t)e * NHEADS + h8]);

    // pass 2: s = sum(exp), acc = sum(exp * v)
    float s = 0.f;
    float acc[8] = {0.f, 0.f, 0.f, 0.f, 0.f, 0.f, 0.f, 0.f};
    for (int e = lo; e < hi; ++e) {
        float a = attn[(size_t)e * NHEADS + h8];
        float ev = expf(a - m);
        s += ev;
        float w = __shfl_sync(0xffffffffu, ev, head);  // lane 'head' holds head's ev
        int se = src[e];
        const float4* vp = (const float4*)(v + (size_t)se * HDIM) + lane * 2;
        float4 v0 = vp[0], v1 = vp[1];
        acc[0] += w * v0.x; acc[1] += w * v0.y; acc[2] += w * v0.z; acc[3] += w * v0.w;
        acc[4] += w * v1.x; acc[5] += w * v1.y; acc[6] += w * v1.z; acc[7] += w * v1.w;
    }
    float sh = __shfl_sync(0xffffffffu, s, head);
    float inv = 1.f / fmaxf(sh, 1e-9f);

    float* op = out + (size_t)node * HDIM + lane * 8;
    *(float4*)op       = make_float4(acc[0] * inv, acc[1] * inv, acc[2] * inv, acc[3] * inv);
    *(float4*)(op + 4) = make_float4(acc[4] * inv, acc[5] * inv, acc[6] * inv, acc[7] * inv);
}

// ---------------- residual + LayerNorm: warp per row -----------------------
__global__ void __launch_bounds__(256) ln_kernel(
    const float* __restrict__ x, const float* __restrict__ t,
    const float* __restrict__ g, const float* __restrict__ b,
    float* __restrict__ out, int M)
{
    int row = (blockIdx.x * blockDim.x + threadIdx.x) >> 5;
    int lane = threadIdx.x & 31;
    if (row >= M) return;

    const float4* xp = (const float4*)(x + (size_t)row * HDIM) + lane * 2;
    const float4* tp = (const float4*)(t + (size_t)row * HDIM) + lane * 2;
    float4 a0 = xp[0], a1 = xp[1], c0 = tp[0], c1 = tp[1];
    float vals[8];
    vals[0] = a0.x + c0.x; vals[1] = a0.y + c0.y; vals[2] = a0.z + c0.z; vals[3] = a0.w + c0.w;
    vals[4] = a1.x + c1.x; vals[5] = a1.y + c1.y; vals[6] = a1.z + c1.z; vals[7] = a1.w + c1.w;

    float sum = 0.f, sq = 0.f;
#pragma unroll
    for (int j = 0; j < 8; ++j) { sum += vals[j]; sq += vals[j] * vals[j]; }
#pragma unroll
    for (int o = 16; o; o >>= 1) {
        sum += __shfl_xor_sync(0xffffffffu, sum, o);
        sq  += __shfl_xor_sync(0xffffffffu, sq,  o);
    }
    float mean = sum * (1.f / HDIM);
    float var  = sq * (1.f / HDIM) - mean * mean;
    float inv  = rsqrtf(var + 1e-5f);

    const float4* gp = (const float4*)(g) + lane * 2;
    const float4* bp = (const float4*)(b) + lane * 2;
    float4 g0 = gp[0], g1 = gp[1], bb0 = bp[0], bb1 = bp[1];

    float* op = out + (size_t)row * HDIM + lane * 8;
    float4 o0, o1;
    o0.x = (vals[0] - mean) * inv * g0.x + bb0.x;
    o0.y = (vals[1] - mean) * inv * g0.y + bb0.y;
    o0.z = (vals[2] - mean) * inv * g0.z + bb0.z;
    o0.w = (vals[3] - mean) * inv * g0.w + bb0.w;
    o1.x = (vals[4] - mean) * inv * g1.x + bb1.x;
    o1.y = (vals[5] - mean) * inv * g1.y + bb1.y;
    o1.z = (vals[6] - mean) * inv * g1.z + bb1.z;
    o1.w = (vals[7] - mean) * inv * g1.w + bb1.w;
    *(float4*)op       = o0;
    *(float4*)(op + 4) = o1;
}

// ---------------------------------------------------------------------------
extern "C" void kernel_launch(void* const* d_in, const int* in_sizes, int n_in,
                              void* d_out, int out_size)
{
    const float* x_paper  = (const float*)d_in[0];
    const float* x_author = (const float*)d_in[1];
    const int* w_src  = (const int*)d_in[2];
    const int* w_dst  = (const int*)d_in[3];
    const int* wr_src = (const int*)d_in[4];
    const int* wr_dst = (const int*)d_in[5];
    const int* c_src  = (const int*)d_in[6];
    const int* c_dst  = (const int*)d_in[7];
    const float* Wq = (const float*)d_in[8];
    const float* bq = (const float*)d_in[9];
    const float* Wk = (const float*)d_in[10];
    const float* bk = (const float*)d_in[11];
    const float* Wv = (const float*)d_in[12];
    const float* bv = (const float*)d_in[13];
    const float* eattn = (const float*)d_in[14];
    const float* Wout_p = (const float*)d_in[15];
    const float* bout_p = (const float*)d_in[16];
    const float* Wout_a = (const float*)d_in[17];
    const float* bout_a = (const float*)d_in[18];
    const float* lng_p = (const float*)d_in[19];
    const float* lnb_p = (const float*)d_in[20];
    const float* lng_a = (const float*)d_in[21];
    const float* lnb_a = (const float*)d_in[22];
    const float* w_paper = (const float*)d_in[23];
    // d_in[24] = w_author (softmax of 1 element == 1.0, unused)

    float* out = (float*)d_out;

    float *q0, *k0, *v0, *q1, *k1, *v1, *q2, *k2, *v2;
    float *at0, *at1, *at2, *aw, *awr, *ac, *tp, *ta;
    cudaGetSymbolAddress((void**)&q0, g_q0);
    cudaGetSymbolAddress((void**)&k0, g_k0);
    cudaGetSymbolAddress((void**)&v0, g_v0);
    cudaGetSymbolAddress((void**)&q1, g_q1);
    cudaGetSymbolAddress((void**)&k1, g_k1);
    cudaGetSymbolAddress((void**)&v1, g_v1);
    cudaGetSymbolAddress((void**)&q2, g_q2);
    cudaGetSymbolAddress((void**)&k2, g_k2);
    cudaGetSymbolAddress((void**)&v2, g_v2);
    cudaGetSymbolAddress((void**)&at0, g_attn0);
    cudaGetSymbolAddress((void**)&at1, g_attn1);
    cudaGetSymbolAddress((void**)&at2, g_attn2);
    cudaGetSymbolAddress((void**)&aw, g_aggw);
    cudaGetSymbolAddress((void**)&awr, g_aggwr);
    cudaGetSymbolAddress((void**)&ac, g_aggc);
    cudaGetSymbolAddress((void**)&tp, g_tmp_p);
    cudaGetSymbolAddress((void**)&ta, g_tmp_a);

    const int HH = HDIM * HDIM;

    auto gemm = [&](const float* A0, const float* A1, const float* wsm,
                    const float* W, const float* bias, float* C, int M) {
        dim3 grid((M + 127) / 128, HDIM / 128);
        gemm_fused<<<grid, 256>>>(A0, A1, wsm, W, bias, C, M);
    };

    // projections (rel 0: writes, rel 1: written_by, rel 2: cites)
    gemm(x_paper,  nullptr, nullptr, Wq + 0 * HH, bq + 0 * HDIM, q0, NPAPER);
    gemm(x_author, nullptr, nullptr, Wk + 0 * HH, bk + 0 * HDIM, k0, NAUTHOR);
    gemm(x_author, nullptr, nullptr, Wv + 0 * HH, bv + 0 * HDIM, v0, NAUTHOR);
    gemm(x_author, nullptr, nullptr, Wq + 1 * HH, bq + 1 * HDIM, q1, NAUTHOR);
    gemm(x_paper,  nullptr, nullptr, Wk + 1 * HH, bk + 1 * HDIM, k1, NPAPER);
    gemm(x_paper,  nullptr, nullptr, Wv + 1 * HH, bv + 1 * HDIM, v1, NPAPER);
    gemm(x_paper,  nullptr, nullptr, Wq + 2 * HH, bq + 2 * HDIM, q2, NPAPER);
    gemm(x_paper,  nullptr, nullptr, Wk + 2 * HH, bk + 2 * HDIM, k2, NPAPER);
    gemm(x_paper,  nullptr, nullptr, Wv + 2 * HH, bv + 2 * HDIM, v2, NPAPER);

    // edge attention scores
    int eblocks = (NEDGE * 32 + 255) / 256;
    edge_attn_kernel<<<eblocks, 256>>>(q0, k0, w_src,  w_dst,  eattn + 0,  at0, NEDGE);
    edge_attn_kernel<<<eblocks, 256>>>(q1, k1, wr_src, wr_dst, eattn + 8,  at1, NEDGE);
    edge_attn_kernel<<<eblocks, 256>>>(q2, k2, c_src,  c_dst,  eattn + 16, at2, NEDGE);

    // segmented softmax + aggregation
    seg_agg_kernel<<<(NPAPER * 32 + 255) / 256, 256>>>(at0, v0, w_src,  w_dst,  aw,  NPAPER,  NEDGE);
    seg_agg_kernel<<<(NAUTHOR * 32 + 255) / 256, 256>>>(at1, v1, wr_src, wr_dst, awr, NAUTHOR, NEDGE);
    seg_agg_kernel<<<(NPAPER * 32 + 255) / 256, 256>>>(at2, v2, c_src,  c_dst,  ac,  NPAPER,  NEDGE);

    // output projections (paper combines writes+cites with softmax(w_paper))
    gemm(aw,  ac,      w_paper, Wout_p, bout_p, tp, NPAPER);
    gemm(awr, nullptr, nullptr, Wout_a, bout_a, ta, NAUTHOR);

    // residual + layernorm -> packed output [paper | author]
    ln_kernel<<<(NPAPER * 32 + 255) / 256, 256>>>(x_paper, tp, lng_p, lnb_p, out, NPAPER);
    ln_kernel<<<(NAUTHOR * 32 + 255) / 256, 256>>>(x_author, ta, lng_a, lnb_a,
                                                   out + (size_t)NPAPER * HDIM, NAUTHOR);
}

// round 5
// speedup vs baseline: 1.4477x; 1.0626x over previous
#include <cuda_runtime.h>
#include <math.h>

#define NPAPER  100000
#define NAUTHOR 50000
#define NEDGE   400000
#define HDIM    256
#define NHEADS  8
#define HD      32

// ---------------- scratch (device globals; no allocation allowed) ----------
__device__ float g_q0[NPAPER * HDIM];
__device__ float g_k0[NAUTHOR * HDIM];
__device__ float g_v0[NAUTHOR * HDIM];
__device__ float g_q1[NAUTHOR * HDIM];
__device__ float g_k1[NPAPER * HDIM];
__device__ float g_v1[NPAPER * HDIM];
__device__ float g_q2[NPAPER * HDIM];
__device__ float g_k2[NPAPER * HDIM];
__device__ float g_v2[NPAPER * HDIM];
__device__ float g_attn0[NEDGE * NHEADS];
__device__ float g_attn1[NEDGE * NHEADS];
__device__ float g_attn2[NEDGE * NHEADS];
__device__ float g_aggw[NPAPER * HDIM];
__device__ float g_aggwr[NAUTHOR * HDIM];
__device__ float g_aggc[NPAPER * HDIM];
__device__ float g_tmp_p[NPAPER * HDIM];
__device__ float g_tmp_a[NAUTHOR * HDIM];
__device__ int   g_offs0[NPAPER + 1];
__device__ int   g_offs1[NAUTHOR + 1];
__device__ int   g_offs2[NPAPER + 1];

// ---------------- GEMM: C[M,256] = (w0*A0 + w1*A1) @ W + bias --------------
// BM=128, BN=128, BK=8, 256 threads, 8x8 register tile per thread.
__global__ void __launch_bounds__(256) gemm_fused(
    const float* __restrict__ A0, const float* __restrict__ A1,
    const float* __restrict__ wsm,   // if non-null: 2-way softmax weights
    const float* __restrict__ W, const float* __restrict__ bias,
    float* __restrict__ C, int M)
{
    __shared__ float As[8][128];
    __shared__ float Bs[8][128];

    const int tid = threadIdx.x;
    const int bm = blockIdx.x * 128;
    const int bn = blockIdx.y * 128;

    float w0 = 1.f, w1 = 0.f;
    if (wsm) {
        float a = wsm[0], b = wsm[1];
        float mx = fmaxf(a, b);
        float e0 = expf(a - mx), e1 = expf(b - mx);
        float inv = 1.f / (e0 + e1);
        w0 = e0 * inv; w1 = e1 * inv;
    }

    const int tm = (tid >> 4) * 8;   // 0..120
    const int tn = (tid & 15) * 8;   // 0..120

    const int arow = tid >> 1;        // 0..127
    const int aseg = (tid & 1) * 4;   // 0 or 4
    const int brow = tid >> 5;        // 0..7
    const int bcol = (tid & 31) * 4;  // 0..124

    const bool arow_ok = (bm + arow) < M;
    const float* Arow0 = A0 + (size_t)(bm + arow) * HDIM;
    const float* Arow1 = A1 ? (A1 + (size_t)(bm + arow) * HDIM) : nullptr;

    float acc[8][8];
#pragma unroll
    for (int i = 0; i < 8; ++i)
#pragma unroll
        for (int j = 0; j < 8; ++j) acc[i][j] = 0.f;

    for (int k0 = 0; k0 < HDIM; k0 += 8) {
        float4 av = make_float4(0.f, 0.f, 0.f, 0.f);
        if (arow_ok) {
            float4 a0 = *(const float4*)(Arow0 + k0 + aseg);
            if (Arow1) {
                float4 a1 = *(const float4*)(Arow1 + k0 + aseg);
                av = make_float4(w0 * a0.x + w1 * a1.x, w0 * a0.y + w1 * a1.y,
                                 w0 * a0.z + w1 * a1.z, w0 * a0.w + w1 * a1.w);
            } else {
                av = make_float4(w0 * a0.x, w0 * a0.y, w0 * a0.z, w0 * a0.w);
            }
        }
        float4 bv = *(const float4*)(W + (size_t)(k0 + brow) * HDIM + bn + bcol);

        __syncthreads();
        As[aseg + 0][arow] = av.x;
        As[aseg + 1][arow] = av.y;
        As[aseg + 2][arow] = av.z;
        As[aseg + 3][arow] = av.w;
        *(float4*)&Bs[brow][bcol] = bv;
        __syncthreads();

#pragma unroll
        for (int k = 0; k < 8; ++k) {
            float a[8], b[8];
            *(float4*)(a)     = *(const float4*)&As[k][tm];
            *(float4*)(a + 4) = *(const float4*)&As[k][tm + 4];
            *(float4*)(b)     = *(const float4*)&Bs[k][tn];
            *(float4*)(b + 4) = *(const float4*)&Bs[k][tn + 4];
#pragma unroll
            for (int i = 0; i < 8; ++i)
#pragma unroll
                for (int j = 0; j < 8; ++j) acc[i][j] += a[i] * b[j];
        }
    }

#pragma unroll
    for (int i = 0; i < 8; ++i) {
        int row = bm + tm + i;
        if (row < M) {
#pragma unroll
            for (int j = 0; j < 8; j += 4) {
                float4 o;
                o.x = acc[i][j + 0] + bias[bn + tn + j + 0];
                o.y = acc[i][j + 1] + bias[bn + tn + j + 1];
                o.z = acc[i][j + 2] + bias[bn + tn + j + 2];
                o.w = acc[i][j + 3] + bias[bn + tn + j + 3];
                *(float4*)&C[(size_t)row * HDIM + bn + tn + j] = o;
            }
        }
    }
}

// ---------------- segment offsets from sorted dst --------------------------
// offs[k] = lower_bound(dst, k) for k in [0, n_dst]
__global__ void __launch_bounds__(256) build_offsets(
    const int* __restrict__ dst, int* __restrict__ offs, int n_dst, int E)
{
    int e = blockIdx.x * blockDim.x + threadIdx.x;
    if (e >= E) return;
    int d = dst[e];
    if (e == 0) {
        for (int k = 0; k <= d; ++k) offs[k] = 0;
    } else {
        int dp = dst[e - 1];
        for (int k = dp + 1; k <= d; ++k) offs[k] = e;
    }
    if (e == E - 1) {
        for (int k = d + 1; k <= n_dst; ++k) offs[k] = E;
    }
}

// ---------------- edge attention scores: warp per edge ---------------------
__global__ void __launch_bounds__(256) edge_attn_kernel(
    const float* __restrict__ q, const float* __restrict__ k,
    const int* __restrict__ src, const int* __restrict__ dst,
    const float* __restrict__ eattn, float* __restrict__ attn, int E)
{
    int e = (blockIdx.x * blockDim.x + threadIdx.x) >> 5;
    int lane = threadIdx.x & 31;
    if (e >= E) return;
    int s = src[e], d = dst[e];
    const float4* qp = (const float4*)(q + (size_t)d * HDIM) + lane * 2;
    const float4* kp = (const float4*)(k + (size_t)s * HDIM) + lane * 2;
    float4 q0 = qp[0], q1 = qp[1];
    float4 k0 = kp[0], k1 = kp[1];
    float p = q0.x * k0.x + q0.y * k0.y + q0.z * k0.z + q0.w * k0.w +
              q1.x * k1.x + q1.y * k1.y + q1.z * k1.z + q1.w * k1.w;
    // reduce within 4-lane groups (one head per group)
    p += __shfl_xor_sync(0xffffffffu, p, 1);
    p += __shfl_xor_sync(0xffffffffu, p, 2);
    if ((lane & 3) == 0) {
        int h = lane >> 2;
        attn[(size_t)e * NHEADS + h] = p * 0.17677669529663687f + eattn[h];
    }
}

// ---------------- segmented softmax + V aggregation: warp per dst node -----
__global__ void __launch_bounds__(256) seg_agg_kernel(
    const float* __restrict__ attn, const float* __restrict__ v,
    const int* __restrict__ src, const int* __restrict__ offs,
    float* __restrict__ out, int n_dst)
{
    int node = (blockIdx.x * blockDim.x + threadIdx.x) >> 5;
    int lane = threadIdx.x & 31;
    if (node >= n_dst) return;

    int lo = offs[node];
    int hi = offs[node + 1];

    const int h8 = lane & 7;     // head this lane tracks for softmax stats
    const int head = lane >> 2;  // head owning this lane's V dims

    // pass 1: per-head max, clamped at 0 (torch index_reduce on zeros buffer)
    float m = 0.f;
    for (int e = lo; e < hi; ++e)
        m = fmaxf(m, attn[(size_t)e * NHEADS + h8]);

    // pass 2: s = sum(exp), acc = sum(exp * v)
    float s = 0.f;
    float acc[8] = {0.f, 0.f, 0.f, 0.f, 0.f, 0.f, 0.f, 0.f};
    for (int e = lo; e < hi; ++e) {
        float a = attn[(size_t)e * NHEADS + h8];
        float ev = __expf(a - m);
        s += ev;
        float w = __shfl_sync(0xffffffffu, ev, head);  // lane 'head' holds head's ev
        int se = src[e];
        const float4* vp = (const float4*)(v + (size_t)se * HDIM) + lane * 2;
        float4 v0 = vp[0], v1 = vp[1];
        acc[0] += w * v0.x; acc[1] += w * v0.y; acc[2] += w * v0.z; acc[3] += w * v0.w;
        acc[4] += w * v1.x; acc[5] += w * v1.y; acc[6] += w * v1.z; acc[7] += w * v1.w;
    }
    float sh = __shfl_sync(0xffffffffu, s, head);
    float inv = 1.f / fmaxf(sh, 1e-9f);

    float* op = out + (size_t)node * HDIM + lane * 8;
    *(float4*)op       = make_float4(acc[0] * inv, acc[1] * inv, acc[2] * inv, acc[3] * inv);
    *(float4*)(op + 4) = make_float4(acc[4] * inv, acc[5] * inv, acc[6] * inv, acc[7] * inv);
}

// ---------------- residual + LayerNorm: warp per row -----------------------
__global__ void __launch_bounds__(256) ln_kernel(
    const float* __restrict__ x, const float* __restrict__ t,
    const float* __restrict__ g, const float* __restrict__ b,
    float* __restrict__ out, int M)
{
    int row = (blockIdx.x * blockDim.x + threadIdx.x) >> 5;
    int lane = threadIdx.x & 31;
    if (row >= M) return;

    const float4* xp = (const float4*)(x + (size_t)row * HDIM) + lane * 2;
    const float4* tp = (const float4*)(t + (size_t)row * HDIM) + lane * 2;
    float4 a0 = xp[0], a1 = xp[1], c0 = tp[0], c1 = tp[1];
    float vals[8];
    vals[0] = a0.x + c0.x; vals[1] = a0.y + c0.y; vals[2] = a0.z + c0.z; vals[3] = a0.w + c0.w;
    vals[4] = a1.x + c1.x; vals[5] = a1.y + c1.y; vals[6] = a1.z + c1.z; vals[7] = a1.w + c1.w;

    float sum = 0.f, sq = 0.f;
#pragma unroll
    for (int j = 0; j < 8; ++j) { sum += vals[j]; sq += vals[j] * vals[j]; }
#pragma unroll
    for (int o = 16; o; o >>= 1) {
        sum += __shfl_xor_sync(0xffffffffu, sum, o);
        sq  += __shfl_xor_sync(0xffffffffu, sq,  o);
    }
    float mean = sum * (1.f / HDIM);
    float var  = sq * (1.f / HDIM) - mean * mean;
    float inv  = rsqrtf(var + 1e-5f);

    const float4* gp = (const float4*)(g) + lane * 2;
    const float4* bp = (const float4*)(b) + lane * 2;
    float4 g0 = gp[0], g1 = gp[1], bb0 = bp[0], bb1 = bp[1];

    float* op = out + (size_t)row * HDIM + lane * 8;
    float4 o0, o1;
    o0.x = (vals[0] - mean) * inv * g0.x + bb0.x;
    o0.y = (vals[1] - mean) * inv * g0.y + bb0.y;
    o0.z = (vals[2] - mean) * inv * g0.z + bb0.z;
    o0.w = (vals[3] - mean) * inv * g0.w + bb0.w;
    o1.x = (vals[4] - mean) * inv * g1.x + bb1.x;
    o1.y = (vals[5] - mean) * inv * g1.y + bb1.y;
    o1.z = (vals[6] - mean) * inv * g1.z + bb1.z;
    o1.w = (vals[7] - mean) * inv * g1.w + bb1.w;
    *(float4*)op       = o0;
    *(float4*)(op + 4) = o1;
}

// ---------------------------------------------------------------------------
extern "C" void kernel_launch(void* const* d_in, const int* in_sizes, int n_in,
                              void* d_out, int out_size)
{
    const float* x_paper  = (const float*)d_in[0];
    const float* x_author = (const float*)d_in[1];
    const int* w_src  = (const int*)d_in[2];
    const int* w_dst  = (const int*)d_in[3];
    const int* wr_src = (const int*)d_in[4];
    const int* wr_dst = (const int*)d_in[5];
    const int* c_src  = (const int*)d_in[6];
    const int* c_dst  = (const int*)d_in[7];
    const float* Wq = (const float*)d_in[8];
    const float* bq = (const float*)d_in[9];
    const float* Wk = (const float*)d_in[10];
    const float* bk = (const float*)d_in[11];
    const float* Wv = (const float*)d_in[12];
    const float* bv = (const float*)d_in[13];
    const float* eattn = (const float*)d_in[14];
    const float* Wout_p = (const float*)d_in[15];
    const float* bout_p = (const float*)d_in[16];
    const float* Wout_a = (const float*)d_in[17];
    const float* bout_a = (const float*)d_in[18];
    const float* lng_p = (const float*)d_in[19];
    const float* lnb_p = (const float*)d_in[20];
    const float* lng_a = (const float*)d_in[21];
    const float* lnb_a = (const float*)d_in[22];
    const float* w_paper = (const float*)d_in[23];
    // d_in[24] = w_author (softmax of 1 element == 1.0, unused)

    float* out = (float*)d_out;

    float *q0, *k0, *v0, *q1, *k1, *v1, *q2, *k2, *v2;
    float *at0, *at1, *at2, *aw, *awr, *ac, *tp, *ta;
    int *of0, *of1, *of2;
    cudaGetSymbolAddress((void**)&q0, g_q0);
    cudaGetSymbolAddress((void**)&k0, g_k0);
    cudaGetSymbolAddress((void**)&v0, g_v0);
    cudaGetSymbolAddress((void**)&q1, g_q1);
    cudaGetSymbolAddress((void**)&k1, g_k1);
    cudaGetSymbolAddress((void**)&v1, g_v1);
    cudaGetSymbolAddress((void**)&q2, g_q2);
    cudaGetSymbolAddress((void**)&k2, g_k2);
    cudaGetSymbolAddress((void**)&v2, g_v2);
    cudaGetSymbolAddress((void**)&at0, g_attn0);
    cudaGetSymbolAddress((void**)&at1, g_attn1);
    cudaGetSymbolAddress((void**)&at2, g_attn2);
    cudaGetSymbolAddress((void**)&aw, g_aggw);
    cudaGetSymbolAddress((void**)&awr, g_aggwr);
    cudaGetSymbolAddress((void**)&ac, g_aggc);
    cudaGetSymbolAddress((void**)&tp, g_tmp_p);
    cudaGetSymbolAddress((void**)&ta, g_tmp_a);
    cudaGetSymbolAddress((void**)&of0, g_offs0);
    cudaGetSymbolAddress((void**)&of1, g_offs1);
    cudaGetSymbolAddress((void**)&of2, g_offs2);

    const int HH = HDIM * HDIM;

    auto gemm = [&](const float* A0, const float* A1, const float* wsm,
                    const float* W, const float* bias, float* C, int M) {
        dim3 grid((M + 127) / 128, HDIM / 128);
        gemm_fused<<<grid, 256>>>(A0, A1, wsm, W, bias, C, M);
    };

    // segment offsets (independent of GEMMs; launch first)
    int oblocks = (NEDGE + 255) / 256;
    build_offsets<<<oblocks, 256>>>(w_dst,  of0, NPAPER,  NEDGE);
    build_offsets<<<oblocks, 256>>>(wr_dst, of1, NAUTHOR, NEDGE);
    build_offsets<<<oblocks, 256>>>(c_dst,  of2, NPAPER,  NEDGE);

    // projections (rel 0: writes, rel 1: written_by, rel 2: cites)
    gemm(x_paper,  nullptr, nullptr, Wq + 0 * HH, bq + 0 * HDIM, q0, NPAPER);
    gemm(x_author, nullptr, nullptr, Wk + 0 * HH, bk + 0 * HDIM, k0, NAUTHOR);
    gemm(x_author, nullptr, nullptr, Wv + 0 * HH, bv + 0 * HDIM, v0, NAUTHOR);
    gemm(x_author, nullptr, nullptr, Wq + 1 * HH, bq + 1 * HDIM, q1, NAUTHOR);
    gemm(x_paper,  nullptr, nullptr, Wk + 1 * HH, bk + 1 * HDIM, k1, NPAPER);
    gemm(x_paper,  nullptr, nullptr, Wv + 1 * HH, bv + 1 * HDIM, v1, NPAPER);
    gemm(x_paper,  nullptr, nullptr, Wq + 2 * HH, bq + 2 * HDIM, q2, NPAPER);
    gemm(x_paper,  nullptr, nullptr, Wk + 2 * HH, bk + 2 * HDIM, k2, NPAPER);
    gemm(x_paper,  nullptr, nullptr, Wv + 2 * HH, bv + 2 * HDIM, v2, NPAPER);

    // edge attention scores
    int eblocks = (NEDGE * 32 + 255) / 256;
    edge_attn_kernel<<<eblocks, 256>>>(q0, k0, w_src,  w_dst,  eattn + 0,  at0, NEDGE);
    edge_attn_kernel<<<eblocks, 256>>>(q1, k1, wr_src, wr_dst, eattn + 8,  at1, NEDGE);
    edge_attn_kernel<<<eblocks, 256>>>(q2, k2, c_src,  c_dst,  eattn + 16, at2, NEDGE);

    // segmented softmax + aggregation (offsets precomputed — no binary search)
    seg_agg_kernel<<<(NPAPER * 32 + 255) / 256, 256>>>(at0, v0, w_src,  of0, aw,  NPAPER);
    seg_agg_kernel<<<(NAUTHOR * 32 + 255) / 256, 256>>>(at1, v1, wr_src, of1, awr, NAUTHOR);
    seg_agg_kernel<<<(NPAPER * 32 + 255) / 256, 256>>>(at2, v2, c_src,  of2, ac,  NPAPER);

    // output projections (paper combines writes+cites with softmax(w_paper))
    gemm(aw,  ac,      w_paper, Wout_p, bout_p, tp, NPAPER);
    gemm(awr, nullptr, nullptr, Wout_a, bout_a, ta, NAUTHOR);

    // residual + layernorm -> packed output [paper | author]
    ln_kernel<<<(NPAPER * 32 + 255) / 256, 256>>>(x_paper, tp, lng_p, lnb_p, out, NPAPER);
    ln_kernel<<<(NAUTHOR * 32 + 255) / 256, 256>>>(x_author, ta, lng_a, lnb_a,
                                                   out + (size_t)NPAPER * HDIM, NAUTHOR);
}

// round 8
// speedup vs baseline: 1.6106x; 1.1125x over previous
#include <cuda_runtime.h>
#include <math.h>

#define NPAPER  100000
#define NAUTHOR 50000
#define NEDGE   400000
#define HDIM    256
#define NHEADS  8
#define HD      32

// ---------------- scratch (device globals; no allocation allowed) ----------
__device__ float g_q0[NPAPER * HDIM];
__device__ float g_k0[NAUTHOR * HDIM];
__device__ float g_v0[NAUTHOR * HDIM];
__device__ float g_q1[NAUTHOR * HDIM];
__device__ float g_k1[NPAPER * HDIM];
__device__ float g_v1[NPAPER * HDIM];
__device__ float g_q2[NPAPER * HDIM];
__device__ float g_k2[NPAPER * HDIM];
__device__ float g_v2[NPAPER * HDIM];
__device__ float g_attn0[NEDGE * NHEADS];
__device__ float g_attn1[NEDGE * NHEADS];
__device__ float g_attn2[NEDGE * NHEADS];
__device__ float g_aggw[NPAPER * HDIM];
__device__ float g_aggwr[NAUTHOR * HDIM];
__device__ float g_aggc[NPAPER * HDIM];
__device__ float g_tmp_p[NPAPER * HDIM];
__device__ float g_tmp_a[NAUTHOR * HDIM];
__device__ int   g_offs0[NPAPER + 1];
__device__ int   g_offs1[NAUTHOR + 1];
__device__ int   g_offs2[NPAPER + 1];

// ---------------- GEMM: C[M,256] = (w0*A0 + w1*A1) @ W + bias --------------
// BM=128, BN=128, BK=8, 256 threads, 8x8 register tile split 4+4
// (rows {tm..tm+3, tm+64..tm+67}, cols {tn..tn+3, tn+64..tn+67}) so every
// LDS.128 phase hits 32 distinct banks (B) or broadcasts (A).
__global__ void __launch_bounds__(256) gemm_fused(
    const float* __restrict__ A0, const float* __restrict__ A1,
    const float* __restrict__ wsm,   // if non-null: 2-way softmax weights
    const float* __restrict__ W, const float* __restrict__ bias,
    float* __restrict__ C, int M)
{
    __shared__ float As[8][128];
    __shared__ float Bs[8][128];

    const int tid = threadIdx.x;
    const int bm = blockIdx.x * 128;
    const int bn = blockIdx.y * 128;

    float w0 = 1.f, w1 = 0.f;
    if (wsm) {
        float a = wsm[0], b = wsm[1];
        float mx = fmaxf(a, b);
        float e0 = expf(a - mx), e1 = expf(b - mx);
        float inv = 1.f / (e0 + e1);
        w0 = e0 * inv; w1 = e1 * inv;
    }

    const int tm = (tid >> 4) * 4;   // 0..60
    const int tn = (tid & 15) * 4;   // 0..60

    const int arow = tid >> 1;        // 0..127
    const int aseg = (tid & 1) * 4;   // 0 or 4
    const int brow = tid >> 5;        // 0..7
    const int bcol = (tid & 31) * 4;  // 0..124

    const bool arow_ok = (bm + arow) < M;
    const float* Arow0 = A0 + (size_t)(bm + arow) * HDIM;
    const float* Arow1 = A1 ? (A1 + (size_t)(bm + arow) * HDIM) : nullptr;

    float acc[8][8];
#pragma unroll
    for (int i = 0; i < 8; ++i)
#pragma unroll
        for (int j = 0; j < 8; ++j) acc[i][j] = 0.f;

    for (int k0 = 0; k0 < HDIM; k0 += 8) {
        float4 av = make_float4(0.f, 0.f, 0.f, 0.f);
        if (arow_ok) {
            float4 a0 = *(const float4*)(Arow0 + k0 + aseg);
            if (Arow1) {
                float4 a1 = *(const float4*)(Arow1 + k0 + aseg);
                av = make_float4(w0 * a0.x + w1 * a1.x, w0 * a0.y + w1 * a1.y,
                                 w0 * a0.z + w1 * a1.z, w0 * a0.w + w1 * a1.w);
            } else {
                av = make_float4(w0 * a0.x, w0 * a0.y, w0 * a0.z, w0 * a0.w);
            }
        }
        float4 bv = *(const float4*)(W + (size_t)(k0 + brow) * HDIM + bn + bcol);

        __syncthreads();
        As[aseg + 0][arow] = av.x;
        As[aseg + 1][arow] = av.y;
        As[aseg + 2][arow] = av.z;
        As[aseg + 3][arow] = av.w;
        *(float4*)&Bs[brow][bcol] = bv;
        __syncthreads();

#pragma unroll
        for (int k = 0; k < 8; ++k) {
            float a[8], b[8];
            *(float4*)(a)     = *(const float4*)&As[k][tm];
            *(float4*)(a + 4) = *(const float4*)&As[k][tm + 64];
            *(float4*)(b)     = *(const float4*)&Bs[k][tn];
            *(float4*)(b + 4) = *(const float4*)&Bs[k][tn + 64];
#pragma unroll
            for (int i = 0; i < 8; ++i)
#pragma unroll
                for (int j = 0; j < 8; ++j) acc[i][j] += a[i] * b[j];
        }
    }

#pragma unroll
    for (int ih = 0; ih < 2; ++ih) {
#pragma unroll
        for (int i = 0; i < 4; ++i) {
            int row = bm + tm + ih * 64 + i;
            if (row < M) {
#pragma unroll
                for (int jh = 0; jh < 2; ++jh) {
                    int col = bn + tn + jh * 64;
                    float4 o;
                    o.x = acc[ih*4+i][jh*4+0] + bias[col + 0];
                    o.y = acc[ih*4+i][jh*4+1] + bias[col + 1];
                    o.z = acc[ih*4+i][jh*4+2] + bias[col + 2];
                    o.w = acc[ih*4+i][jh*4+3] + bias[col + 3];
                    *(float4*)&C[(size_t)row * HDIM + col] = o;
                }
            }
        }
    }
}

// ---------------- segment offsets from sorted dst --------------------------
__global__ void __launch_bounds__(256) build_offsets(
    const int* __restrict__ dst, int* __restrict__ offs, int n_dst, int E)
{
    int e = blockIdx.x * blockDim.x + threadIdx.x;
    if (e >= E) return;
    int d = dst[e];
    if (e == 0) {
        for (int k = 0; k <= d; ++k) offs[k] = 0;
    } else {
        int dp = dst[e - 1];
        for (int k = dp + 1; k <= d; ++k) offs[k] = e;
    }
    if (e == E - 1) {
        for (int k = d + 1; k <= n_dst; ++k) offs[k] = E;
    }
}

// ---------------- edge attention scores: warp per edge ---------------------
__global__ void __launch_bounds__(256) edge_attn_kernel(
    const float* __restrict__ q, const float* __restrict__ k,
    const int* __restrict__ src, const int* __restrict__ dst,
    const float* __restrict__ eattn, float* __restrict__ attn, int E)
{
    int e = (blockIdx.x * blockDim.x + threadIdx.x) >> 5;
    int lane = threadIdx.x & 31;
    if (e >= E) return;
    int s = src[e], d = dst[e];
    const float4* qp = (const float4*)(q + (size_t)d * HDIM) + lane * 2;
    const float4* kp = (const float4*)(k + (size_t)s * HDIM) + lane * 2;
    float4 q0 = qp[0], q1 = qp[1];
    float4 k0 = kp[0], k1 = kp[1];
    float p = q0.x * k0.x + q0.y * k0.y + q0.z * k0.z + q0.w * k0.w +
              q1.x * k1.x + q1.y * k1.y + q1.z * k1.z + q1.w * k1.w;
    p += __shfl_xor_sync(0xffffffffu, p, 1);
    p += __shfl_xor_sync(0xffffffffu, p, 2);
    if ((lane & 3) == 0) {
        int h = lane >> 2;
        attn[(size_t)e * NHEADS + h] = p * 0.17677669529663687f + eattn[h];
    }
}

// ---------------- segmented softmax + V aggregation: warp per dst node -----
// pass 2 is software-pipelined: edge e+1's attn/src/v loads issue while
// edge e's accumulation runs.
__global__ void __launch_bounds__(256) seg_agg_kernel(
    const float* __restrict__ attn, const float* __restrict__ v,
    const int* __restrict__ src, const int* __restrict__ offs,
    float* __restrict__ out, int n_dst)
{
    int node = (blockIdx.x * blockDim.x + threadIdx.x) >> 5;
    int lane = threadIdx.x & 31;
    if (node >= n_dst) return;

    int lo = offs[node];
    int hi = offs[node + 1];

    const int h8 = lane & 7;
    const int head = lane >> 2;

    // pass 1: per-head max, clamped at 0 (torch index_reduce on zeros buffer)
    float m = 0.f;
    for (int e = lo; e < hi; ++e)
        m = fmaxf(m, attn[(size_t)e * NHEADS + h8]);

    // pass 2: s = sum(exp), acc = sum(exp * v) — 2-stage pipeline
    float s = 0.f;
    float acc[8] = {0.f, 0.f, 0.f, 0.f, 0.f, 0.f, 0.f, 0.f};

    float a_cur = 0.f;
    float4 x0 = make_float4(0.f, 0.f, 0.f, 0.f);
    float4 x1 = make_float4(0.f, 0.f, 0.f, 0.f);
    if (lo < hi) {
        a_cur = attn[(size_t)lo * NHEADS + h8];
        const float4* vp = (const float4*)(v + (size_t)src[lo] * HDIM) + lane * 2;
        x0 = vp[0]; x1 = vp[1];
    }
    for (int e = lo; e < hi; ++e) {
        int en = e + 1;
        float a_nxt = 0.f;
        float4 y0, y1;
        if (en < hi) {
            a_nxt = attn[(size_t)en * NHEADS + h8];
            const float4* vp = (const float4*)(v + (size_t)src[en] * HDIM) + lane * 2;
            y0 = vp[0]; y1 = vp[1];
        } else {
            y0 = make_float4(0.f, 0.f, 0.f, 0.f);
            y1 = make_float4(0.f, 0.f, 0.f, 0.f);
        }
        float ev = __expf(a_cur - m);
        s += ev;
        float w = __shfl_sync(0xffffffffu, ev, head);
        acc[0] += w * x0.x; acc[1] += w * x0.y; acc[2] += w * x0.z; acc[3] += w * x0.w;
        acc[4] += w * x1.x; acc[5] += w * x1.y; acc[6] += w * x1.z; acc[7] += w * x1.w;
        a_cur = a_nxt; x0 = y0; x1 = y1;
    }
    float sh = __shfl_sync(0xffffffffu, s, head);
    float inv = 1.f / fmaxf(sh, 1e-9f);

    float* op = out + (size_t)node * HDIM + lane * 8;
    *(float4*)op       = make_float4(acc[0] * inv, acc[1] * inv, acc[2] * inv, acc[3] * inv);
    *(float4*)(op + 4) = make_float4(acc[4] * inv, acc[5] * inv, acc[6] * inv, acc[7] * inv);
}

// ---------------- residual + LayerNorm: warp per row -----------------------
__global__ void __launch_bounds__(256) ln_kernel(
    const float* __restrict__ x, const float* __restrict__ t,
    const float* __restrict__ g, const float* __restrict__ b,
    float* __restrict__ out, int M)
{
    int row = (blockIdx.x * blockDim.x + threadIdx.x) >> 5;
    int lane = threadIdx.x & 31;
    if (row >= M) return;

    const float4* xp = (const float4*)(x + (size_t)row * HDIM) + lane * 2;
    const float4* tp = (const float4*)(t + (size_t)row * HDIM) + lane * 2;
    float4 a0 = xp[0], a1 = xp[1], c0 = tp[0], c1 = tp[1];
    float vals[8];
    vals[0] = a0.x + c0.x; vals[1] = a0.y + c0.y; vals[2] = a0.z + c0.z; vals[3] = a0.w + c0.w;
    vals[4] = a1.x + c1.x; vals[5] = a1.y + c1.y; vals[6] = a1.z + c1.z; vals[7] = a1.w + c1.w;

    float sum = 0.f, sq = 0.f;
#pragma unroll
    for (int j = 0; j < 8; ++j) { sum += vals[j]; sq += vals[j] * vals[j]; }
#pragma unroll
    for (int o = 16; o; o >>= 1) {
        sum += __shfl_xor_sync(0xffffffffu, sum, o);
        sq  += __shfl_xor_sync(0xffffffffu, sq,  o);
    }
    float mean = sum * (1.f / HDIM);
    float var  = sq * (1.f / HDIM) - mean * mean;
    float inv  = rsqrtf(var + 1e-5f);

    const float4* gp = (const float4*)(g) + lane * 2;
    const float4* bp = (const float4*)(b) + lane * 2;
    float4 g0 = gp[0], g1 = gp[1], bb0 = bp[0], bb1 = bp[1];

    float* op = out + (size_t)row * HDIM + lane * 8;
    float4 o0, o1;
    o0.x = (vals[0] - mean) * inv * g0.x + bb0.x;
    o0.y = (vals[1] - mean) * inv * g0.y + bb0.y;
    o0.z = (vals[2] - mean) * inv * g0.z + bb0.z;
    o0.w = (vals[3] - mean) * inv * g0.w + bb0.w;
    o1.x = (vals[4] - mean) * inv * g1.x + bb1.x;
    o1.y = (vals[5] - mean) * inv * g1.y + bb1.y;
    o1.z = (vals[6] - mean) * inv * g1.z + bb1.z;
    o1.w = (vals[7] - mean) * inv * g1.w + bb1.w;
    *(float4*)op       = o0;
    *(float4*)(op + 4) = o1;
}

// ---------------------------------------------------------------------------
extern "C" void kernel_launch(void* const* d_in, const int* in_sizes, int n_in,
                              void* d_out, int out_size)
{
    const float* x_paper  = (const float*)d_in[0];
    const float* x_author = (const float*)d_in[1];
    const int* w_src  = (const int*)d_in[2];
    const int* w_dst  = (const int*)d_in[3];
    const int* wr_src = (const int*)d_in[4];
    const int* wr_dst = (const int*)d_in[5];
    const int* c_src  = (const int*)d_in[6];
    const int* c_dst  = (const int*)d_in[7];
    const float* Wq = (const float*)d_in[8];
    const float* bq = (const float*)d_in[9];
    const float* Wk = (const float*)d_in[10];
    const float* bk = (const float*)d_in[11];
    const float* Wv = (const float*)d_in[12];
    const float* bv = (const float*)d_in[13];
    const float* eattn = (const float*)d_in[14];
    const float* Wout_p = (const float*)d_in[15];
    const float* bout_p = (const float*)d_in[16];
    const float* Wout_a = (const float*)d_in[17];
    const float* bout_a = (const float*)d_in[18];
    const float* lng_p = (const float*)d_in[19];
    const float* lnb_p = (const float*)d_in[20];
    const float* lng_a = (const float*)d_in[21];
    const float* lnb_a = (const float*)d_in[22];
    const float* w_paper = (const float*)d_in[23];
    // d_in[24] = w_author (softmax of 1 element == 1.0, unused)

    float* out = (float*)d_out;

    float *q0, *k0, *v0, *q1, *k1, *v1, *q2, *k2, *v2;
    float *at0, *at1, *at2, *aw, *awr, *ac, *tp, *ta;
    int *of0, *of1, *of2;
    cudaGetSymbolAddress((void**)&q0, g_q0);
    cudaGetSymbolAddress((void**)&k0, g_k0);
    cudaGetSymbolAddress((void**)&v0, g_v0);
    cudaGetSymbolAddress((void**)&q1, g_q1);
    cudaGetSymbolAddress((void**)&k1, g_k1);
    cudaGetSymbolAddress((void**)&v1, g_v1);
    cudaGetSymbolAddress((void**)&q2, g_q2);
    cudaGetSymbolAddress((void**)&k2, g_k2);
    cudaGetSymbolAddress((void**)&v2, g_v2);
    cudaGetSymbolAddress((void**)&at0, g_attn0);
    cudaGetSymbolAddress((void**)&at1, g_attn1);
    cudaGetSymbolAddress((void**)&at2, g_attn2);
    cudaGetSymbolAddress((void**)&aw, g_aggw);
    cudaGetSymbolAddress((void**)&awr, g_aggwr);
    cudaGetSymbolAddress((void**)&ac, g_aggc);
    cudaGetSymbolAddress((void**)&tp, g_tmp_p);
    cudaGetSymbolAddress((void**)&ta, g_tmp_a);
    cudaGetSymbolAddress((void**)&of0, g_offs0);
    cudaGetSymbolAddress((void**)&of1, g_offs1);
    cudaGetSymbolAddress((void**)&of2, g_offs2);

    const int HH = HDIM * HDIM;

    auto gemm = [&](const float* A0, const float* A1, const float* wsm,
                    const float* W, const float* bias, float* C, int M) {
        dim3 grid((M + 127) / 128, HDIM / 128);
        gemm_fused<<<grid, 256>>>(A0, A1, wsm, W, bias, C, M);
    };

    // segment offsets
    int oblocks = (NEDGE + 255) / 256;
    build_offsets<<<oblocks, 256>>>(w_dst,  of0, NPAPER,  NEDGE);
    build_offsets<<<oblocks, 256>>>(wr_dst, of1, NAUTHOR, NEDGE);
    build_offsets<<<oblocks, 256>>>(c_dst,  of2, NPAPER,  NEDGE);

    // projections (rel 0: writes, rel 1: written_by, rel 2: cites)
    gemm(x_paper,  nullptr, nullptr, Wq + 0 * HH, bq + 0 * HDIM, q0, NPAPER);
    gemm(x_author, nullptr, nullptr, Wk + 0 * HH, bk + 0 * HDIM, k0, NAUTHOR);
    gemm(x_author, nullptr, nullptr, Wv + 0 * HH, bv + 0 * HDIM, v0, NAUTHOR);
    gemm(x_author, nullptr, nullptr, Wq + 1 * HH, bq + 1 * HDIM, q1, NAUTHOR);
    gemm(x_paper,  nullptr, nullptr, Wk + 1 * HH, bk + 1 * HDIM, k1, NPAPER);
    gemm(x_paper,  nullptr, nullptr, Wv + 1 * HH, bv + 1 * HDIM, v1, NPAPER);
    gemm(x_paper,  nullptr, nullptr, Wq + 2 * HH, bq + 2 * HDIM, q2, NPAPER);
    gemm(x_paper,  nullptr, nullptr, Wk + 2 * HH, bk + 2 * HDIM, k2, NPAPER);
    gemm(x_paper,  nullptr, nullptr, Wv + 2 * HH, bv + 2 * HDIM, v2, NPAPER);

    // edge attention scores
    int eblocks = (NEDGE * 32 + 255) / 256;
    edge_attn_kernel<<<eblocks, 256>>>(q0, k0, w_src,  w_dst,  eattn + 0,  at0, NEDGE);
    edge_attn_kernel<<<eblocks, 256>>>(q1, k1, wr_src, wr_dst, eattn + 8,  at1, NEDGE);
    edge_attn_kernel<<<eblocks, 256>>>(q2, k2, c_src,  c_dst,  eattn + 16, at2, NEDGE);

    // segmented softmax + aggregation (offsets precomputed)
    seg_agg_kernel<<<(NPAPER * 32 + 255) / 256, 256>>>(at0, v0, w_src,  of0, aw,  NPAPER);
    seg_agg_kernel<<<(NAUTHOR * 32 + 255) / 256, 256>>>(at1, v1, wr_src, of1, awr, NAUTHOR);
    seg_agg_kernel<<<(NPAPER * 32 + 255) / 256, 256>>>(at2, v2, c_src,  of2, ac,  NPAPER);

    // output projections (paper combines writes+cites with softmax(w_paper))
    gemm(aw,  ac,      w_paper, Wout_p, bout_p, tp, NPAPER);
    gemm(awr, nullptr, nullptr, Wout_a, bout_a, ta, NAUTHOR);

    // residual + layernorm -> packed output [paper | author]
    ln_kernel<<<(NPAPER * 32 + 255) / 256, 256>>>(x_paper, tp, lng_p, lnb_p, out, NPAPER);
    ln_kernel<<<(NAUTHOR * 32 + 255) / 256, 256>>>(x_author, ta, lng_a, lnb_a,
                                                   out + (size_t)NPAPER * HDIM, NAUTHOR);
}